// round 14
// baseline (speedup 1.0000x reference)
#include <cuda_runtime.h>
#include <cstdint>

// TotalDegree: out[b,t] = monomials of degree<=4 over x[b,0..7], 495 terms,
// lexicographic multiset (preorder-DFS) order.
//
// R14 = R13 (quad-row float4-interleaved gather, rotation-aligned streaming
// stores) + SINGLE-WAVE grid: each warp handles 8 rows {r+32k, k=0..7} as two
// quad passes. 8192 warps -> 2048 blocks < 2432 resident capacity: the whole
// grid runs as ONE wave (no quantization tail, perfect balance).

#define NTERMS 495
#define NVALS  45          // pair values (a,b), 0 <= a <= b <= 8; index 8 == 1.0
#define DIM    8
#define NITER  16          // 512-padded term space
#define NTHREADS 128
#define RSTRIDE 32         // row spacing within a quad
#define QUAD    4
#define PASSES  2          // 8 rows per warp

constexpr int vid(int a, int b) { return a * 9 - a * (a - 1) / 2 + (b - a); }

struct T16 { unsigned short v[512]; };
struct Dec { unsigned char v[NVALS]; };

constexpr T16 make_tbl() {
    T16 t{};
    int n = 0;
    const int one = vid(8, 8);                                   // id 44 -> 1.0
    t.v[n++] = (unsigned short)(one | (one << 8));               // degree 0
    for (int a = 0; a < DIM; a++) {
        t.v[n++] = (unsigned short)(vid(a, 8) | (one << 8));     // degree 1
        for (int b = a; b < DIM; b++) {
            t.v[n++] = (unsigned short)(vid(a, b) | (one << 8)); // degree 2
            for (int c = b; c < DIM; c++) {
                t.v[n++] = (unsigned short)(vid(a, b) | (vid(c, 8) << 8));      // deg 3
                for (int d = c; d < DIM; d++)
                    t.v[n++] = (unsigned short)(vid(a, b) | (vid(c, d) << 8));  // deg 4
            }
        }
    }
    for (int k = n; k < 512; k++) t.v[k] = (unsigned short)(one | (one << 8));
    return t;
}

constexpr Dec make_dec() {
    Dec d{};
    for (int a = 0; a <= 8; a++)
        for (int b = a; b <= 8; b++)
            d.v[vid(a, b)] = (unsigned char)(a | (b << 4));
    return d;
}

__device__ const T16 g_tbl = make_tbl();
__device__ const Dec g_dec = make_dec();

__global__ void __launch_bounds__(NTHREADS)
totaldegree_kernel(const float* __restrict__ x, float* __restrict__ out, int nrows) {
    __shared__ float4 s_v4[NTHREADS / 32][48];     // interleaved quad pair-values
    __shared__ unsigned short s_tbl[512];

    const int warp = threadIdx.x >> 5;
    const int lane = threadIdx.x & 31;

    // stage term table once per block (512 u16 = 256 u32; 128 threads x 2)
    ((unsigned*)s_tbl)[threadIdx.x]       = ((const unsigned*)g_tbl.v)[threadIdx.x];
    ((unsigned*)s_tbl)[threadIdx.x + 128] = ((const unsigned*)g_tbl.v)[threadIdx.x + 128];
    __syncthreads();

    // warp W owns rows rowA0 + 32k, k=0..7, inside a 256-row window
    const int W = blockIdx.x * (NTHREADS / 32) + warp;
    const int rowA0 = ((W >> 5) << 8) + (W & 31);

    const unsigned d0 = g_dec.v[lane];
    const unsigned d1 = g_dec.v[(lane + 32 < NVALS) ? lane + 32 : NVALS - 1];

    // rotation: 495*rowA0 + s0 == 0 (mod 32); invariant under +32k
    const unsigned s0 = ((unsigned)rowA0 * 17u) & 31u;

    #pragma unroll 1
    for (int p = 0; p < PASSES; p++) {
        const int rowA = rowA0 + p * (QUAD * RSTRIDE);          // +128 per pass
        if (rowA >= nrows) break;                               // warp-uniform

        bool has[QUAD];
        float v0[QUAD], v1[QUAD];
        #pragma unroll
        for (int q = 0; q < QUAD; q++) {
            const int row = rowA + q * RSTRIDE;
            has[q] = (row < nrows);
            float xv = 1.0f;
            if (has[q] && lane < DIM) xv = x[(size_t)row * DIM + lane];
            const float a0 = __shfl_sync(0xffffffffu, xv, d0 & 15u);
            const float b0 = __shfl_sync(0xffffffffu, xv, d0 >> 4);
            const float a1 = __shfl_sync(0xffffffffu, xv, d1 & 15u);
            const float b1 = __shfl_sync(0xffffffffu, xv, d1 >> 4);
            v0[q] = a0 * b0;
            v1[q] = a1 * b1;
        }
        __syncwarp();                        // prior pass's V4 reads complete
        s_v4[warp][lane] = make_float4(v0[0], v0[1], v0[2], v0[3]);
        if (lane < NVALS - 32)
            s_v4[warp][lane + 32] = make_float4(v1[0], v1[1], v1[2], v1[3]);
        __syncwarp();                        // V4 visible to whole warp

        const char* V4b = (const char*)s_v4[warp];
        float* oA = out + (size_t)rowA * NTERMS;   // rows B/C/D at const offsets

        #pragma unroll
        for (int i = 0; i < NITER; i++) {
            const unsigned tidx = (s0 + 32u * i + lane) & 511u;   // rotated term id
            const unsigned p2 = s_tbl[tidx];                       // ONE read, 4 rows
            const float4 flo = *(const float4*)(V4b + ((p2 & 255u) << 4));
            const float4 fhi = *(const float4*)(V4b + ((p2 >> 8)   << 4));
            if (tidx < NTERMS) {                                   // drop pad slots
                __stcs(oA + tidx, flo.x * fhi.x);
                if (has[1]) __stcs(oA + 1 * RSTRIDE * NTERMS + tidx, flo.y * fhi.y);
                if (has[2]) __stcs(oA + 2 * RSTRIDE * NTERMS + tidx, flo.z * fhi.z);
                if (has[3]) __stcs(oA + 3 * RSTRIDE * NTERMS + tidx, flo.w * fhi.w);
            }
        }
    }
}

extern "C" void kernel_launch(void* const* d_in, const int* in_sizes, int n_in,
                              void* d_out, int out_size) {
    const float* x = (const float*)d_in[0];
    float* out = (float*)d_out;
    const int nrows = in_sizes[0] / DIM;
    const int warps_needed = (nrows + QUAD * RSTRIDE * PASSES / 32 - 1) / 8;  // 8 rows/warp
    const int blocks = (warps_needed + (NTHREADS / 32) - 1) / (NTHREADS / 32); // 2048
    totaldegree_kernel<<<blocks, NTHREADS>>>(x, out, nrows);
}

// round 15
// speedup vs baseline: 1.0755x; 1.0755x over previous
#include <cuda_runtime.h>
#include <cstdint>

// TotalDegree: out[b,t] = monomials of degree<=4 over x[b,0..7], 495 terms,
// lexicographic multiset (preorder-DFS) order.
//
// R15 = R10's grid (2 rows/warp: r and r+32 share rotation s0; 8192 blocks of
// 128 thr -> occ ~87%, small wave tail) + R13's vectorized gather idea at
// float2 width: V tables for the row pair interleaved as float2 (8B stride,
// LDS.64, inherently aligned). Inner iter: 1 tbl LDS.U16 + 2 LDS.64 + 2 FMUL
// + 2 rotation-aligned streaming STG.

#define NTERMS 495
#define NVALS  45          // pair values (a,b), 0 <= a <= b <= 8; index 8 == 1.0
#define DIM    8
#define NITER  16          // 512-padded term space
#define NTHREADS 128

constexpr int vid(int a, int b) { return a * 9 - a * (a - 1) / 2 + (b - a); }

struct T16 { unsigned short v[512]; };
struct Dec { unsigned char v[NVALS]; };

constexpr T16 make_tbl() {
    T16 t{};
    int n = 0;
    const int one = vid(8, 8);                                   // id 44 -> 1.0
    t.v[n++] = (unsigned short)(one | (one << 8));               // degree 0
    for (int a = 0; a < DIM; a++) {
        t.v[n++] = (unsigned short)(vid(a, 8) | (one << 8));     // degree 1
        for (int b = a; b < DIM; b++) {
            t.v[n++] = (unsigned short)(vid(a, b) | (one << 8)); // degree 2
            for (int c = b; c < DIM; c++) {
                t.v[n++] = (unsigned short)(vid(a, b) | (vid(c, 8) << 8));      // deg 3
                for (int d = c; d < DIM; d++)
                    t.v[n++] = (unsigned short)(vid(a, b) | (vid(c, d) << 8));  // deg 4
            }
        }
    }
    for (int k = n; k < 512; k++) t.v[k] = (unsigned short)(one | (one << 8));
    return t;
}

constexpr Dec make_dec() {
    Dec d{};
    for (int a = 0; a <= 8; a++)
        for (int b = a; b <= 8; b++)
            d.v[vid(a, b)] = (unsigned char)(a | (b << 4));
    return d;
}

__device__ const T16 g_tbl = make_tbl();
__device__ const Dec g_dec = make_dec();

__global__ void __launch_bounds__(NTHREADS)
totaldegree_kernel(const float* __restrict__ x, float* __restrict__ out, int nrows) {
    __shared__ float2 s_v2[NTHREADS / 32][48];     // row-pair interleaved V tables
    __shared__ unsigned short s_tbl[512];

    const int warp = threadIdx.x >> 5;
    const int lane = threadIdx.x & 31;

    // stage term table (512 u16 = 256 u32; 128 threads x 2)
    ((unsigned*)s_tbl)[threadIdx.x]       = ((const unsigned*)g_tbl.v)[threadIdx.x];
    ((unsigned*)s_tbl)[threadIdx.x + 128] = ((const unsigned*)g_tbl.v)[threadIdx.x + 128];

    // global warp id -> row pair (rowA, rowA+32) within a 64-row window
    const int W = blockIdx.x * (NTHREADS / 32) + warp;
    const int rowA = ((W >> 5) << 6) + (W & 31);
    const int rowB = rowA + 32;

    float xa = 1.0f, xb = 1.0f;
    if (rowA < nrows && lane < DIM) xa = x[(size_t)rowA * DIM + lane];
    if (rowB < nrows && lane < DIM) xb = x[(size_t)rowB * DIM + lane];

    // build both 45-entry pair-value tables via warp shuffles
    const unsigned d0 = g_dec.v[lane];
    const unsigned d1 = g_dec.v[(lane + 32 < NVALS) ? lane + 32 : NVALS - 1];
    const float aA0 = __shfl_sync(0xffffffffu, xa, d0 & 15u);
    const float bA0 = __shfl_sync(0xffffffffu, xa, d0 >> 4);
    const float aA1 = __shfl_sync(0xffffffffu, xa, d1 & 15u);
    const float bA1 = __shfl_sync(0xffffffffu, xa, d1 >> 4);
    const float aB0 = __shfl_sync(0xffffffffu, xb, d0 & 15u);
    const float bB0 = __shfl_sync(0xffffffffu, xb, d0 >> 4);
    const float aB1 = __shfl_sync(0xffffffffu, xb, d1 & 15u);
    const float bB1 = __shfl_sync(0xffffffffu, xb, d1 >> 4);
    s_v2[warp][lane] = make_float2(aA0 * bA0, aB0 * bB0);        // STS.64
    if (lane < NVALS - 32)
        s_v2[warp][lane + 32] = make_float2(aA1 * bA1, aB1 * bB1);
    __syncthreads();                       // table + V2 visible

    if (rowA >= nrows) return;             // warp-uniform
    const bool hasB = (rowB < nrows);

    const char* V2b = (const char*)s_v2[warp];

    // shared rotation: 495*rowA + s0 == 0 (mod 32); rowB = rowA+32 -> same s0
    const unsigned s0 = ((unsigned)rowA * 17u) & 31u;
    float* oA = out + (size_t)rowA * NTERMS;
    float* oB = out + (size_t)rowB * NTERMS;

    #pragma unroll
    for (int i = 0; i < NITER; i++) {
        const unsigned tidx = (s0 + 32u * i + lane) & 511u;   // rotated term id
        const unsigned p = s_tbl[tidx];                        // ONE read, 2 rows
        const float2 flo = *(const float2*)(V2b + ((p & 255u) << 3));  // LDS.64
        const float2 fhi = *(const float2*)(V2b + ((p >> 8)   << 3));  // LDS.64
        if (tidx < NTERMS) {                                   // drop 17 pad slots
            __stcs(oA + tidx, flo.x * fhi.x);  // 128B-line-aligned streaming stores
            if (hasB) __stcs(oB + tidx, flo.y * fhi.y);
        }
    }
}

extern "C" void kernel_launch(void* const* d_in, const int* in_sizes, int n_in,
                              void* d_out, int out_size) {
    const float* x = (const float*)d_in[0];
    float* out = (float*)d_out;
    const int nrows = in_sizes[0] / DIM;
    const int warps_needed = (nrows + 1) / 2;                         // 2 rows/warp
    const int blocks = (warps_needed + (NTHREADS / 32) - 1) / (NTHREADS / 32); // 8192
    totaldegree_kernel<<<blocks, NTHREADS>>>(x, out, nrows);
}

// round 16
// speedup vs baseline: 1.0890x; 1.0125x over previous
#include <cuda_runtime.h>
#include <cstdint>

// TotalDegree: out[b,t] = monomials of degree<=4 over x[b,0..7], 495 terms,
// lexicographic multiset (preorder-DFS) order.
//
// R16 = R13's quad-row float4-interleaved gather (lowest instruction count:
// 1 tbl LDS.U16 + 2 LDS.128 + 4 FMUL + 4 aligned streaming STG per iter,
// serving 4 rows) on a FINER grid: 64-thread blocks -> 8192 blocks, so the
// 1.68-wave tail schedules at fine granularity (R13's only deficit vs R11).

#define NTERMS 495
#define NVALS  45          // pair values (a,b), 0 <= a <= b <= 8; index 8 == 1.0
#define DIM    8
#define NITER  16          // 512-padded term space
#define NTHREADS 64        // 2 warps per block -> fine-grained tail balancing
#define RSTRIDE 32         // row spacing within a quad
#define QUAD    4

constexpr int vid(int a, int b) { return a * 9 - a * (a - 1) / 2 + (b - a); }

struct T16 { unsigned short v[512]; };
struct Dec { unsigned char v[NVALS]; };

constexpr T16 make_tbl() {
    T16 t{};
    int n = 0;
    const int one = vid(8, 8);                                   // id 44 -> 1.0
    t.v[n++] = (unsigned short)(one | (one << 8));               // degree 0
    for (int a = 0; a < DIM; a++) {
        t.v[n++] = (unsigned short)(vid(a, 8) | (one << 8));     // degree 1
        for (int b = a; b < DIM; b++) {
            t.v[n++] = (unsigned short)(vid(a, b) | (one << 8)); // degree 2
            for (int c = b; c < DIM; c++) {
                t.v[n++] = (unsigned short)(vid(a, b) | (vid(c, 8) << 8));      // deg 3
                for (int d = c; d < DIM; d++)
                    t.v[n++] = (unsigned short)(vid(a, b) | (vid(c, d) << 8));  // deg 4
            }
        }
    }
    for (int k = n; k < 512; k++) t.v[k] = (unsigned short)(one | (one << 8));
    return t;
}

constexpr Dec make_dec() {
    Dec d{};
    for (int a = 0; a <= 8; a++)
        for (int b = a; b <= 8; b++)
            d.v[vid(a, b)] = (unsigned char)(a | (b << 4));
    return d;
}

__device__ const T16 g_tbl = make_tbl();
__device__ const Dec g_dec = make_dec();

__global__ void __launch_bounds__(NTHREADS)
totaldegree_kernel(const float* __restrict__ x, float* __restrict__ out, int nrows) {
    __shared__ float4 s_v4[NTHREADS / 32][48];     // interleaved quad pair-values
    __shared__ unsigned short s_tbl[512];

    const int warp = threadIdx.x >> 5;
    const int lane = threadIdx.x & 31;

    // stage term table (512 u16 = 256 u32; 64 threads x 4)
    {
        const unsigned* src = (const unsigned*)g_tbl.v;
        unsigned* dst = (unsigned*)s_tbl;
        #pragma unroll
        for (int k = 0; k < 4; k++)
            dst[threadIdx.x + 64 * k] = src[threadIdx.x + 64 * k];
    }

    // global warp id -> base row of its quad, within a 128-row window
    const int W = blockIdx.x * (NTHREADS / 32) + warp;
    const int rowA = ((W >> 5) << 7) + (W & 31);   // rows rowA + 32*q, q=0..3

    const unsigned d0 = g_dec.v[lane];
    const unsigned d1 = g_dec.v[(lane + 32 < NVALS) ? lane + 32 : NVALS - 1];

    bool has[QUAD];
    float v0[QUAD], v1[QUAD];                       // this lane's V[lane], V[lane+32]
    #pragma unroll
    for (int q = 0; q < QUAD; q++) {
        const int row = rowA + q * RSTRIDE;
        has[q] = (row < nrows);
        float xv = 1.0f;
        if (has[q] && lane < DIM) xv = x[(size_t)row * DIM + lane];
        const float a0 = __shfl_sync(0xffffffffu, xv, d0 & 15u);
        const float b0 = __shfl_sync(0xffffffffu, xv, d0 >> 4);
        const float a1 = __shfl_sync(0xffffffffu, xv, d1 & 15u);
        const float b1 = __shfl_sync(0xffffffffu, xv, d1 >> 4);
        v0[q] = a0 * b0;
        v1[q] = a1 * b1;
    }
    // interleaved build: one STS.128 per owned index
    s_v4[warp][lane] = make_float4(v0[0], v0[1], v0[2], v0[3]);
    if (lane < NVALS - 32)
        s_v4[warp][lane + 32] = make_float4(v1[0], v1[1], v1[2], v1[3]);
    __syncthreads();                       // table + V4 visible

    if (rowA >= nrows) return;             // warp-uniform

    const char* V4b = (const char*)s_v4[warp];

    // shared rotation: 495*rowA + s0 == 0 (mod 32); +32k rows keep same s0
    const unsigned s0 = ((unsigned)rowA * 17u) & 31u;
    float* oA = out + (size_t)rowA * NTERMS;       // rows B/C/D at const offsets

    #pragma unroll
    for (int i = 0; i < NITER; i++) {
        const unsigned tidx = (s0 + 32u * i + lane) & 511u;   // rotated term id
        const unsigned p = s_tbl[tidx];                        // ONE read, 4 rows
        const float4 flo = *(const float4*)(V4b + ((p & 255u) << 4));  // LDS.128
        const float4 fhi = *(const float4*)(V4b + ((p >> 8)   << 4));  // LDS.128
        if (tidx < NTERMS) {                                   // drop 17 pad slots
            __stcs(oA + tidx, flo.x * fhi.x);
            if (has[1]) __stcs(oA + 1 * RSTRIDE * NTERMS + tidx, flo.y * fhi.y);
            if (has[2]) __stcs(oA + 2 * RSTRIDE * NTERMS + tidx, flo.z * fhi.z);
            if (has[3]) __stcs(oA + 3 * RSTRIDE * NTERMS + tidx, flo.w * fhi.w);
        }
    }
}

extern "C" void kernel_launch(void* const* d_in, const int* in_sizes, int n_in,
                              void* d_out, int out_size) {
    const float* x = (const float*)d_in[0];
    float* out = (float*)d_out;
    const int nrows = in_sizes[0] / DIM;
    const int warps_needed = (nrows + QUAD - 1) / QUAD;               // 4 rows/warp
    const int blocks = (warps_needed + (NTHREADS / 32) - 1) / (NTHREADS / 32); // 8192
    totaldegree_kernel<<<blocks, NTHREADS>>>(x, out, nrows);
}